// round 6
// baseline (speedup 1.0000x reference)
#include <cuda_runtime.h>
#include <math.h>
#include <stdint.h>

#define CCH    64
#define HWP    3136
#define MTOT   401408
#define CPI    49            // 64-col chunks per image
#define NCHUNK 6272
#define GRIDB  296
#define NS_T   10
#define PG     80            // gram tile pitch (floats): conflict-free frag loads
#define PA     68            // apply tile pitch

typedef unsigned long long u64;

__device__ float d_gram[4096];
__device__ float d_sums[64];
__device__ float d_sumsq[64];
__device__ float d_wm[4096];
__device__ float d_off[64];

// ---- helpers ---------------------------------------------------------------
__device__ __forceinline__ uint32_t fu(float x) { return __float_as_uint(x); }
__device__ __forceinline__ uint32_t tf32r(float x) {
    uint32_t r; asm("cvt.rna.tf32.f32 %0, %1;" : "=r"(r) : "f"(x)); return r;
}
// D += A(16x8,row) * B(8x8,col), tf32 inputs, fp32 accum
__device__ __forceinline__ void mma8(float c[4], uint32_t a0, uint32_t a1,
                                     uint32_t a2, uint32_t a3,
                                     uint32_t b0, uint32_t b1) {
    asm("mma.sync.aligned.m16n8k8.row.col.f32.tf32.tf32.f32 "
        "{%0,%1,%2,%3}, {%4,%5,%6,%7}, {%8,%9}, {%0,%1,%2,%3};"
        : "+f"(c[0]), "+f"(c[1]), "+f"(c[2]), "+f"(c[3])
        : "r"(a0), "r"(a1), "r"(a2), "r"(a3), "r"(b0), "r"(b1));
}
__device__ __forceinline__ void fma2(u64 &acc, u64 a, u64 b) {
    asm("fma.rn.f32x2 %0, %1, %2, %0;" : "+l"(acc) : "l"(a), "l"(b));
}
__device__ __forceinline__ u64 dup2(float x) {
    u64 r; asm("mov.b64 %0, {%1, %1};" : "=l"(r) : "r"(__float_as_uint(x))); return r;
}
__device__ __forceinline__ float2 unpk(u64 v) {
    float2 f; asm("mov.b64 {%0, %1}, %2;" : "=f"(f.x), "=f"(f.y) : "l"(v)); return f;
}
__device__ __forceinline__ void cpa16(uint32_t dst, const float* src) {
    asm volatile("cp.async.ca.shared.global [%0], [%1], 16;" :: "r"(dst), "l"(src));
}
__device__ __forceinline__ void cp_commit() { asm volatile("cp.async.commit_group;"); }
__device__ __forceinline__ void cp_wait1()  { asm volatile("cp.async.wait_group 1;" ::: "memory"); }
__device__ __forceinline__ void cp_wait0()  { asm volatile("cp.async.wait_group 0;" ::: "memory"); }

__global__ void zero_scratch() {
    int i = blockIdx.x * 256 + threadIdx.x;
    if (i < 4096) d_gram[i] = 0.f;
    if (i < 64)   { d_sums[i] = 0.f; d_sumsq[i] = 0.f; }
}

// ---------------------------------------------------------------------------
// Kernel 1: Gram via tf32 mma + exact scalar sums/sumsq (diag override).
// Warp w: rows mb=(w&3)*16, cols nb=(w>>2)*32 (4 n8-tiles).
// k = positions; permuted-k float4 fragment loads, conflict-free at pitch 80.
// ---------------------------------------------------------------------------
__global__ __launch_bounds__(256, 2) void gram_kernel(const float* __restrict__ X) {
    __shared__ __align__(16) float xsh[2][64 * PG];
    int tid = threadIdx.x, lane = tid & 31, w = tid >> 5;
    int g = lane >> 2, t = lane & 3;
    int mb = (w & 3) * 16, nb = (w >> 2) * 32;

    uint32_t sb[2];
    sb[0] = (uint32_t)__cvta_generic_to_shared(&xsh[0][0]);
    sb[1] = (uint32_t)__cvta_generic_to_shared(&xsh[1][0]);

    float acc[4][4];
#pragma unroll
    for (int j = 0; j < 4; j++)
#pragma unroll
        for (int e = 0; e < 4; e++) acc[j][e] = 0.f;
    float csum = 0.f, cq = 0.f;

    // preload first chunk
    {
        int ch = blockIdx.x;
        int b = ch / CPI, pc = (ch - b * CPI) * 64;
        const float* base = X + b * CCH * HWP + pc;
#pragma unroll
        for (int i = 0; i < 4; i++) {
            int f = tid + 256 * i;
            int c = f >> 4, q = f & 15;
            cpa16(sb[0] + (c * PG + q * 4) * 4, base + c * HWP + q * 4);
        }
        cp_commit();
    }

    int buf = 0;
    for (int ch = blockIdx.x; ch < NCHUNK; ch += GRIDB) {
        int cn = ch + GRIDB;
        if (cn < NCHUNK) {
            int b = cn / CPI, pc = (cn - b * CPI) * 64;
            const float* base = X + b * CCH * HWP + pc;
#pragma unroll
            for (int i = 0; i < 4; i++) {
                int f = tid + 256 * i;
                int c = f >> 4, q = f & 15;
                cpa16(sb[buf ^ 1] + (c * PG + q * 4) * 4, base + c * HWP + q * 4);
            }
            cp_commit();
            cp_wait1();
        } else {
            cp_wait0();
        }
        __syncthreads();

        const float* xb = &xsh[buf][0];

        if (tid < 64) {            // exact fp32 sums and sumsq (warps 0-1)
            const float4* r = (const float4*)&xb[tid * PG];
            float s = 0.f, q2 = 0.f;
#pragma unroll
            for (int q = 0; q < 16; q++) {
                float4 v = r[q];
                s  += (v.x + v.y) + (v.z + v.w);
                q2 += v.x * v.x + v.y * v.y + v.z * v.z + v.w * v.w;
            }
            csum += s; cq += q2;
        }

#pragma unroll
        for (int kg = 0; kg < 2; kg++) {
            int kb = kg * 32;
            float4 Al  = *(const float4*)&xb[(mb + g)     * PG + kb + 4 * t];
            float4 Ah  = *(const float4*)&xb[(mb + g)     * PG + kb + 16 + 4 * t];
            float4 A2l = *(const float4*)&xb[(mb + g + 8) * PG + kb + 4 * t];
            float4 A2h = *(const float4*)&xb[(mb + g + 8) * PG + kb + 16 + 4 * t];
#pragma unroll
            for (int j = 0; j < 4; j++) {
                float4 Bl = *(const float4*)&xb[(nb + 8 * j + g) * PG + kb + 4 * t];
                float4 Bh = *(const float4*)&xb[(nb + 8 * j + g) * PG + kb + 16 + 4 * t];
                mma8(acc[j], fu(Al.x), fu(A2l.x), fu(Ah.x), fu(A2h.x), fu(Bl.x), fu(Bh.x));
                mma8(acc[j], fu(Al.y), fu(A2l.y), fu(Ah.y), fu(A2h.y), fu(Bl.y), fu(Bh.y));
                mma8(acc[j], fu(Al.z), fu(A2l.z), fu(Ah.z), fu(A2h.z), fu(Bl.z), fu(Bh.z));
                mma8(acc[j], fu(Al.w), fu(A2l.w), fu(Ah.w), fu(A2h.w), fu(Bl.w), fu(Bh.w));
            }
        }
        __syncthreads();
        buf ^= 1;
    }

#pragma unroll
    for (int j = 0; j < 4; j++) {
        int col = nb + 8 * j + 2 * t;
        atomicAdd(&d_gram[(mb + g)     * 64 + col],     acc[j][0]);
        atomicAdd(&d_gram[(mb + g)     * 64 + col + 1], acc[j][1]);
        atomicAdd(&d_gram[(mb + g + 8) * 64 + col],     acc[j][2]);
        atomicAdd(&d_gram[(mb + g + 8) * 64 + col + 1], acc[j][3]);
    }
    if (tid < 64) { atomicAdd(&d_sums[tid], csum); atomicAdd(&d_sumsq[tid], cq); }
}

// ---------------------------------------------------------------------------
// Kernel 2: Sigma + Newton-Schulz (exact fp32; diag from exact sumsq;
// first iteration folded analytically: P1 = 1.5 I - 0.5 Sigma_N).
// ---------------------------------------------------------------------------
__device__ __forceinline__ void mm_sym(const float* __restrict__ A,
                                       const float* __restrict__ Bm,
                                       int ib, int jb, u64 acc[4][2]) {
#pragma unroll
    for (int ii = 0; ii < 4; ii++) { acc[ii][0] = 0ull; acc[ii][1] = 0ull; }
#pragma unroll 8
    for (int k = 0; k < 64; k++) {
        float4 a = *(const float4*)&A[k * 64 + ib];
        ulonglong2 bv = *(const ulonglong2*)&Bm[k * 64 + jb];
        u64 d0 = dup2(a.x), d1 = dup2(a.y), d2 = dup2(a.z), d3 = dup2(a.w);
        fma2(acc[0][0], d0, bv.x); fma2(acc[0][1], d0, bv.y);
        fma2(acc[1][0], d1, bv.x); fma2(acc[1][1], d1, bv.y);
        fma2(acc[2][0], d2, bv.x); fma2(acc[2][1], d2, bv.y);
        fma2(acc[3][0], d3, bv.x); fma2(acc[3][1], d3, bv.y);
    }
}

__device__ __forceinline__ void store4(float* __restrict__ D, int ib, int jb,
                                       u64 acc[4][2]) {
#pragma unroll
    for (int ii = 0; ii < 4; ii++) {
        float2 l0 = unpk(acc[ii][0]);
        float2 l1 = unpk(acc[ii][1]);
        *(float4*)&D[(ib + ii) * 64 + jb] = make_float4(l0.x, l0.y, l1.x, l1.y);
    }
}

__global__ __launch_bounds__(256) void ns_kernel(const float* __restrict__ beta) {
    __shared__ __align__(16) float B0[4096];  // P
    __shared__ __align__(16) float B1[4096];  // Sigma_N
    __shared__ __align__(16) float B2[4096];  // P^2
    __shared__ __align__(16) float B3[4096];  // P^3
    int tid = threadIdx.x;
    int ib = (tid >> 4) * 4;
    int jb = (tid & 15) * 4;
    const float inv_m = 1.f / (float)MTOT;

    for (int idx = tid; idx < 4096; idx += 256) {
        int i = idx >> 6, j = idx & 63;
        float mi = d_sums[i] * inv_m, mj = d_sums[j] * inv_m;
        float s;
        if (i == j) s = d_sumsq[i] * inv_m - mi * mi + 1e-5f;   // exact diag
        else        s = (d_gram[idx] * inv_m - mi * mj) * 0.9f;
        B1[idx] = s;
    }
    __syncthreads();

    if (tid < 32) {
        float s = B1[tid * 64 + tid] + B1[(tid + 32) * 64 + (tid + 32)];
#pragma unroll
        for (int o = 16; o > 0; o >>= 1) s += __shfl_xor_sync(0xffffffffu, s, o);
        if (tid == 0) B2[0] = s;
    }
    __syncthreads();
    float rTr = 1.f / B2[0];
    float srt = sqrtf(rTr);
    __syncthreads();

    // Sigma_N and P1 = 1.5 I - 0.5 Sigma_N (first NS iteration, exact)
    for (int idx = tid; idx < 4096; idx += 256) {
        int i = idx >> 6, j = idx & 63;
        float sn = B1[idx] * rTr;
        B1[idx] = sn;
        B0[idx] = (i == j ? 1.5f : 0.f) - 0.5f * sn;
    }
    __syncthreads();

    u64 acc[4][2];
    for (int it = 0; it < NS_T - 1; it++) {
        mm_sym(B0, B0, ib, jb, acc);       // P^2
        store4(B2, ib, jb, acc);
        __syncthreads();
        mm_sym(B2, B0, ib, jb, acc);       // P^3
        store4(B3, ib, jb, acc);
        __syncthreads();
        mm_sym(B3, B1, ib, jb, acc);       // P^3 @ Sigma_N
#pragma unroll
        for (int ii = 0; ii < 4; ii++) {
            float2 l0 = unpk(acc[ii][0]);
            float2 l1 = unpk(acc[ii][1]);
            int base = (ib + ii) * 64 + jb;
            float4 p = *(const float4*)&B0[base];
            *(float4*)&B0[base] = make_float4(1.5f * p.x - 0.5f * l0.x,
                                              1.5f * p.y - 0.5f * l0.y,
                                              1.5f * p.z - 0.5f * l1.x,
                                              1.5f * p.w - 0.5f * l1.y);
        }
        __syncthreads();
    }

#pragma unroll
    for (int ii = 0; ii < 4; ii++) {
        int base = (ib + ii) * 64 + jb;
        float4 p = *(const float4*)&B0[base];
        *(float4*)&d_wm[base] = make_float4(p.x * srt, p.y * srt, p.z * srt, p.w * srt);
    }
    if (tid < 64) {
        float s = 0.f;
#pragma unroll 8
        for (int j = 0; j < 64; j++) s += B0[tid * 64 + j] * (d_sums[j] * inv_m);
        d_off[tid] = beta[tid] - srt * s;
    }
}

// ---------------------------------------------------------------------------
// Kernel 3: out = x + E @ x + off,  E = wm - I in tf32 (resident A-frags).
// Warp w: rows mb=(w&1)*32 (2 m16 tiles), cols nb=(w>>1)*16 (2 n8 tiles).
// ---------------------------------------------------------------------------
__global__ __launch_bounds__(256, 2) void apply_kernel(const float* __restrict__ X,
                                                       float* __restrict__ out) {
    __shared__ __align__(16) float xsh[2][64 * PA];
    __shared__ float osh[64];
    int tid = threadIdx.x, lane = tid & 31, w = tid >> 5;
    int g = lane >> 2, t = lane & 3;
    int mb = (w & 1) * 32, nb = (w >> 1) * 16;

    uint32_t sb[2];
    sb[0] = (uint32_t)__cvta_generic_to_shared(&xsh[0][0]);
    sb[1] = (uint32_t)__cvta_generic_to_shared(&xsh[1][0]);

    // resident E fragments (tf32, rna)
    uint32_t ea[2][8][4];
#pragma unroll
    for (int mi = 0; mi < 2; mi++) {
        int r0 = mb + 16 * mi + g, r1 = r0 + 8;
#pragma unroll
        for (int ks = 0; ks < 8; ks++) {
            int c0 = 8 * ks + t, c1 = c0 + 4;
            ea[mi][ks][0] = tf32r(d_wm[r0 * 64 + c0] - (r0 == c0 ? 1.f : 0.f));
            ea[mi][ks][1] = tf32r(d_wm[r1 * 64 + c0] - (r1 == c0 ? 1.f : 0.f));
            ea[mi][ks][2] = tf32r(d_wm[r0 * 64 + c1] - (r0 == c1 ? 1.f : 0.f));
            ea[mi][ks][3] = tf32r(d_wm[r1 * 64 + c1] - (r1 == c1 ? 1.f : 0.f));
        }
    }
    if (tid < 64) osh[tid] = d_off[tid];

    {   // preload first chunk
        int ch = blockIdx.x;
        int b = ch / CPI, pc = (ch - b * CPI) * 64;
        const float* base = X + b * CCH * HWP + pc;
#pragma unroll
        for (int i = 0; i < 4; i++) {
            int f = tid + 256 * i;
            int c = f >> 4, q = f & 15;
            cpa16(sb[0] + (c * PA + q * 4) * 4, base + c * HWP + q * 4);
        }
        cp_commit();
    }

    int buf = 0;
    for (int ch = blockIdx.x; ch < NCHUNK; ch += GRIDB) {
        int cn = ch + GRIDB;
        if (cn < NCHUNK) {
            int b = cn / CPI, pc = (cn - b * CPI) * 64;
            const float* base = X + b * CCH * HWP + pc;
#pragma unroll
            for (int i = 0; i < 4; i++) {
                int f = tid + 256 * i;
                int c = f >> 4, q = f & 15;
                cpa16(sb[buf ^ 1] + (c * PA + q * 4) * 4, base + c * HWP + q * 4);
            }
            cp_commit();
            cp_wait1();
        } else {
            cp_wait0();
        }
        __syncthreads();

        const float* xb = &xsh[buf][0];
        float acc[2][2][4];
#pragma unroll
        for (int mi = 0; mi < 2; mi++) {
            int r0 = mb + 16 * mi + g, r1 = r0 + 8;
            float o0 = osh[r0], o1 = osh[r1];
#pragma unroll
            for (int j = 0; j < 2; j++) {
                int cc = nb + 8 * j + 2 * t;
                float2 v0 = *(const float2*)&xb[r0 * PA + cc];
                float2 v1 = *(const float2*)&xb[r1 * PA + cc];
                acc[mi][j][0] = o0 + v0.x; acc[mi][j][1] = o0 + v0.y;
                acc[mi][j][2] = o1 + v1.x; acc[mi][j][3] = o1 + v1.y;
            }
        }

#pragma unroll
        for (int ks = 0; ks < 8; ks++) {
            uint32_t b00 = fu(xb[(8 * ks + t)     * PA + nb + g]);
            uint32_t b01 = fu(xb[(8 * ks + t + 4) * PA + nb + g]);
            uint32_t b10 = fu(xb[(8 * ks + t)     * PA + nb + 8 + g]);
            uint32_t b11 = fu(xb[(8 * ks + t + 4) * PA + nb + 8 + g]);
#pragma unroll
            for (int mi = 0; mi < 2; mi++) {
                mma8(acc[mi][0], ea[mi][ks][0], ea[mi][ks][1],
                                 ea[mi][ks][2], ea[mi][ks][3], b00, b01);
                mma8(acc[mi][1], ea[mi][ks][0], ea[mi][ks][1],
                                 ea[mi][ks][2], ea[mi][ks][3], b10, b11);
            }
        }

        int b = ch / CPI, pc = (ch - b * CPI) * 64;
        float* ob = out + b * CCH * HWP + pc;
#pragma unroll
        for (int mi = 0; mi < 2; mi++) {
            int r0 = mb + 16 * mi + g, r1 = r0 + 8;
#pragma unroll
            for (int j = 0; j < 2; j++) {
                int cc = nb + 8 * j + 2 * t;
                *(float2*)&ob[r0 * HWP + cc] = make_float2(acc[mi][j][0], acc[mi][j][1]);
                *(float2*)&ob[r1 * HWP + cc] = make_float2(acc[mi][j][2], acc[mi][j][3]);
            }
        }
        __syncthreads();
        buf ^= 1;
    }
}

extern "C" void kernel_launch(void* const* d_in, const int* in_sizes, int n_in,
                              void* d_out, int out_size) {
    (void)in_sizes; (void)n_in; (void)out_size;
    const float* X    = (const float*)d_in[0];
    const float* beta = (const float*)d_in[1];
    float* out        = (float*)d_out;

    zero_scratch<<<17, 256>>>();
    gram_kernel<<<GRIDB, 256>>>(X);
    ns_kernel<<<1, 256>>>(beta);
    apply_kernel<<<GRIDB, 256>>>(X, out);
}

// round 7
// speedup vs baseline: 1.5249x; 1.5249x over previous
#include <cuda_runtime.h>
#include <math.h>
#include <stdint.h>

#define CCH    64
#define HWP    3136
#define MTOT   401408
#define CPI    49
#define NCHUNK 6272
#define GRIDB  296
#define PG     80           // gram tile pitch
#define PA     68           // apply tile pitch
#define PN     68           // ns matrix pitch (conflict-free frag loads)
#define NS_TF  7            // tf32 NS iters (after analytic first)
#define NS_FP  2            // exact fp32 NS iters at the end

typedef unsigned long long u64;

__device__ float d_gpart[GRIDB * 4096];
__device__ float d_spart[GRIDB * 64];
__device__ float d_qpart[GRIDB * 64];
__device__ float d_gram[4096];
__device__ float d_sums[64];
__device__ float d_sumsq[64];
__device__ float d_wm[4096];
__device__ float d_off[64];

// ---- helpers ---------------------------------------------------------------
__device__ __forceinline__ uint32_t fu(float x) { return __float_as_uint(x); }
__device__ __forceinline__ uint32_t tf32r(float x) {
    uint32_t r; asm("cvt.rna.tf32.f32 %0, %1;" : "=r"(r) : "f"(x)); return r;
}
__device__ __forceinline__ void mma8(float c[4], uint32_t a0, uint32_t a1,
                                     uint32_t a2, uint32_t a3,
                                     uint32_t b0, uint32_t b1) {
    asm("mma.sync.aligned.m16n8k8.row.col.f32.tf32.tf32.f32 "
        "{%0,%1,%2,%3}, {%4,%5,%6,%7}, {%8,%9}, {%0,%1,%2,%3};"
        : "+f"(c[0]), "+f"(c[1]), "+f"(c[2]), "+f"(c[3])
        : "r"(a0), "r"(a1), "r"(a2), "r"(a3), "r"(b0), "r"(b1));
}
__device__ __forceinline__ void fma2(u64 &acc, u64 a, u64 b) {
    asm("fma.rn.f32x2 %0, %1, %2, %0;" : "+l"(acc) : "l"(a), "l"(b));
}
__device__ __forceinline__ u64 dup2(float x) {
    u64 r; asm("mov.b64 %0, {%1, %1};" : "=l"(r) : "r"(__float_as_uint(x))); return r;
}
__device__ __forceinline__ float2 unpk(u64 v) {
    float2 f; asm("mov.b64 {%0, %1}, %2;" : "=f"(f.x), "=f"(f.y) : "l"(v)); return f;
}
__device__ __forceinline__ void cpa16(uint32_t dst, const float* src) {
    asm volatile("cp.async.ca.shared.global [%0], [%1], 16;" :: "r"(dst), "l"(src));
}
__device__ __forceinline__ void cp_commit() { asm volatile("cp.async.commit_group;"); }
__device__ __forceinline__ void cp_wait1()  { asm volatile("cp.async.wait_group 1;" ::: "memory"); }
__device__ __forceinline__ void cp_wait0()  { asm volatile("cp.async.wait_group 0;" ::: "memory"); }

// ---------------------------------------------------------------------------
// Kernel 1: Gram via tf32 mma + exact fp32 sums/sumsq. Per-CTA partial output
// (no contended atomics).
// ---------------------------------------------------------------------------
__global__ __launch_bounds__(256, 2) void gram_kernel(const float* __restrict__ X) {
    __shared__ __align__(16) float xsh[2][64 * PG];
    int tid = threadIdx.x, lane = tid & 31, w = tid >> 5;
    int g = lane >> 2, t = lane & 3;
    int mb = (w & 3) * 16, nb = (w >> 2) * 32;

    uint32_t sb[2];
    sb[0] = (uint32_t)__cvta_generic_to_shared(&xsh[0][0]);
    sb[1] = (uint32_t)__cvta_generic_to_shared(&xsh[1][0]);

    float acc[4][4];
#pragma unroll
    for (int j = 0; j < 4; j++)
#pragma unroll
        for (int e = 0; e < 4; e++) acc[j][e] = 0.f;
    float csum = 0.f, cq = 0.f;

    {
        int ch = blockIdx.x;
        int b = ch / CPI, pc = (ch - b * CPI) * 64;
        const float* base = X + b * CCH * HWP + pc;
#pragma unroll
        for (int i = 0; i < 4; i++) {
            int f = tid + 256 * i;
            int c = f >> 4, q = f & 15;
            cpa16(sb[0] + (c * PG + q * 4) * 4, base + c * HWP + q * 4);
        }
        cp_commit();
    }

    int buf = 0;
    for (int ch = blockIdx.x; ch < NCHUNK; ch += GRIDB) {
        int cn = ch + GRIDB;
        if (cn < NCHUNK) {
            int b = cn / CPI, pc = (cn - b * CPI) * 64;
            const float* base = X + b * CCH * HWP + pc;
#pragma unroll
            for (int i = 0; i < 4; i++) {
                int f = tid + 256 * i;
                int c = f >> 4, q = f & 15;
                cpa16(sb[buf ^ 1] + (c * PG + q * 4) * 4, base + c * HWP + q * 4);
            }
            cp_commit();
            cp_wait1();
        } else {
            cp_wait0();
        }
        __syncthreads();

        const float* xb = &xsh[buf][0];

        if (tid < 64) {
            const float4* r = (const float4*)&xb[tid * PG];
            float s = 0.f, q2 = 0.f;
#pragma unroll
            for (int q = 0; q < 16; q++) {
                float4 v = r[q];
                s  += (v.x + v.y) + (v.z + v.w);
                q2 += v.x * v.x + v.y * v.y + v.z * v.z + v.w * v.w;
            }
            csum += s; cq += q2;
        }

#pragma unroll
        for (int kg = 0; kg < 2; kg++) {
            int kb = kg * 32;
            float4 Al  = *(const float4*)&xb[(mb + g)     * PG + kb + 4 * t];
            float4 Ah  = *(const float4*)&xb[(mb + g)     * PG + kb + 16 + 4 * t];
            float4 A2l = *(const float4*)&xb[(mb + g + 8) * PG + kb + 4 * t];
            float4 A2h = *(const float4*)&xb[(mb + g + 8) * PG + kb + 16 + 4 * t];
#pragma unroll
            for (int j = 0; j < 4; j++) {
                float4 Bl = *(const float4*)&xb[(nb + 8 * j + g) * PG + kb + 4 * t];
                float4 Bh = *(const float4*)&xb[(nb + 8 * j + g) * PG + kb + 16 + 4 * t];
                mma8(acc[j], fu(Al.x), fu(A2l.x), fu(Ah.x), fu(A2h.x), fu(Bl.x), fu(Bh.x));
                mma8(acc[j], fu(Al.y), fu(A2l.y), fu(Ah.y), fu(A2h.y), fu(Bl.y), fu(Bh.y));
                mma8(acc[j], fu(Al.z), fu(A2l.z), fu(Ah.z), fu(A2h.z), fu(Bl.z), fu(Bh.z));
                mma8(acc[j], fu(Al.w), fu(A2l.w), fu(Ah.w), fu(A2h.w), fu(Bl.w), fu(Bh.w));
            }
        }
        __syncthreads();
        buf ^= 1;
    }

    float* gp = &d_gpart[blockIdx.x * 4096];
#pragma unroll
    for (int j = 0; j < 4; j++) {
        int col = nb + 8 * j + 2 * t;
        gp[(mb + g)     * 64 + col]     = acc[j][0];
        gp[(mb + g)     * 64 + col + 1] = acc[j][1];
        gp[(mb + g + 8) * 64 + col]     = acc[j][2];
        gp[(mb + g + 8) * 64 + col + 1] = acc[j][3];
    }
    if (tid < 64) {
        d_spart[blockIdx.x * 64 + tid] = csum;
        d_qpart[blockIdx.x * 64 + tid] = cq;
    }
}

// ---------------------------------------------------------------------------
// Kernel 1b: reduce per-CTA partials (no same-address atomics anywhere).
// ---------------------------------------------------------------------------
__global__ __launch_bounds__(128) void reduce_kernel() {
    int idx = blockIdx.x * 128 + threadIdx.x;
    if (idx < 4096) {
        float s = 0.f;
#pragma unroll 4
        for (int c = 0; c < GRIDB; c++) s += d_gpart[c * 4096 + idx];
        d_gram[idx] = s;
    } else if (idx < 4160) {
        int j = idx - 4096;
        float s = 0.f;
#pragma unroll 4
        for (int c = 0; c < GRIDB; c++) s += d_spart[c * 64 + j];
        d_sums[j] = s;
    } else if (idx < 4224) {
        int j = idx - 4160;
        float s = 0.f;
#pragma unroll 4
        for (int c = 0; c < GRIDB; c++) s += d_qpart[c * 64 + j];
        d_sumsq[j] = s;
    }
}

// ---------------------------------------------------------------------------
// Kernel 2: Sigma + Newton-Schulz. Iter 1 analytic, iters 2..8 tf32 mma,
// final 2 iters exact fp32 f32x2. All matrices fp32 in smem, pitch PN=68.
// ---------------------------------------------------------------------------
__device__ __forceinline__ void mm_tf(const float* __restrict__ A,
                                      const float* __restrict__ Bm,
                                      int g, int t, int mb, int nb,
                                      float acc[4][4]) {
#pragma unroll
    for (int j = 0; j < 4; j++)
#pragma unroll
        for (int e = 0; e < 4; e++) acc[j][e] = 0.f;
#pragma unroll
    for (int ks = 0; ks < 8; ks++) {
        uint32_t a0 = fu(A[(mb + g)     * PN + 8 * ks + t]);
        uint32_t a1 = fu(A[(mb + g + 8) * PN + 8 * ks + t]);
        uint32_t a2 = fu(A[(mb + g)     * PN + 8 * ks + t + 4]);
        uint32_t a3 = fu(A[(mb + g + 8) * PN + 8 * ks + t + 4]);
#pragma unroll
        for (int j = 0; j < 4; j++) {
            uint32_t b0 = fu(Bm[(8 * ks + t)     * PN + nb + 8 * j + g]);
            uint32_t b1 = fu(Bm[(8 * ks + t + 4) * PN + nb + 8 * j + g]);
            mma8(acc[j], a0, a1, a2, a3, b0, b1);
        }
    }
}

__device__ __forceinline__ void st_tf(float* __restrict__ D, int g, int t,
                                      int mb, int nb, const float acc[4][4]) {
#pragma unroll
    for (int j = 0; j < 4; j++) {
        int c0 = nb + 8 * j + 2 * t;
        *(float2*)&D[(mb + g)     * PN + c0] = make_float2(acc[j][0], acc[j][1]);
        *(float2*)&D[(mb + g + 8) * PN + c0] = make_float2(acc[j][2], acc[j][3]);
    }
}

__device__ __forceinline__ void mm_sym(const float* __restrict__ A,
                                       const float* __restrict__ Bm,
                                       int ib, int jb, u64 acc[4][2]) {
#pragma unroll
    for (int ii = 0; ii < 4; ii++) { acc[ii][0] = 0ull; acc[ii][1] = 0ull; }
#pragma unroll 8
    for (int k = 0; k < 64; k++) {
        float4 a = *(const float4*)&A[k * PN + ib];
        ulonglong2 bv = *(const ulonglong2*)&Bm[k * PN + jb];
        u64 d0 = dup2(a.x), d1 = dup2(a.y), d2 = dup2(a.z), d3 = dup2(a.w);
        fma2(acc[0][0], d0, bv.x); fma2(acc[0][1], d0, bv.y);
        fma2(acc[1][0], d1, bv.x); fma2(acc[1][1], d1, bv.y);
        fma2(acc[2][0], d2, bv.x); fma2(acc[2][1], d2, bv.y);
        fma2(acc[3][0], d3, bv.x); fma2(acc[3][1], d3, bv.y);
    }
}

__device__ __forceinline__ void store4(float* __restrict__ D, int ib, int jb,
                                       u64 acc[4][2]) {
#pragma unroll
    for (int ii = 0; ii < 4; ii++) {
        float2 l0 = unpk(acc[ii][0]);
        float2 l1 = unpk(acc[ii][1]);
        *(float4*)&D[(ib + ii) * PN + jb] = make_float4(l0.x, l0.y, l1.x, l1.y);
    }
}

__global__ __launch_bounds__(256) void ns_kernel(const float* __restrict__ beta) {
    __shared__ __align__(16) float B0[64 * PN];  // P
    __shared__ __align__(16) float B1[64 * PN];  // Sigma_N
    __shared__ __align__(16) float B2[64 * PN];  // temp P^2
    __shared__ __align__(16) float B3[64 * PN];  // temp P^3
    int tid = threadIdx.x, lane = tid & 31, w = tid >> 5;
    int g = lane >> 2, t = lane & 3;
    int mb = (w & 3) * 16, nb = (w >> 2) * 32;
    int ib = (tid >> 4) * 4, jb = (tid & 15) * 4;
    const float inv_m = 1.f / (float)MTOT;

    for (int idx = tid; idx < 4096; idx += 256) {
        int i = idx >> 6, j = idx & 63;
        float mi = d_sums[i] * inv_m, mj = d_sums[j] * inv_m;
        float s;
        if (i == j) s = d_sumsq[i] * inv_m - mi * mi + 1e-5f;
        else        s = (d_gram[idx] * inv_m - mi * mj) * 0.9f;
        B1[i * PN + j] = s;
    }
    __syncthreads();

    if (tid < 32) {
        float s = B1[tid * PN + tid] + B1[(tid + 32) * PN + (tid + 32)];
#pragma unroll
        for (int o = 16; o > 0; o >>= 1) s += __shfl_xor_sync(0xffffffffu, s, o);
        if (tid == 0) B2[0] = s;
    }
    __syncthreads();
    float rTr = 1.f / B2[0];
    float srt = sqrtf(rTr);
    __syncthreads();

    // Sigma_N, and analytic first iteration: P1 = 1.5I - 0.5 Sigma_N
    for (int idx = tid; idx < 4096; idx += 256) {
        int i = idx >> 6, j = idx & 63;
        float sn = B1[i * PN + j] * rTr;
        B1[i * PN + j] = sn;
        B0[i * PN + j] = (i == j ? 1.5f : 0.f) - 0.5f * sn;
    }
    __syncthreads();

    // tf32 iterations (noise contracted quadratically by later iterations)
    float a4[4][4];
    for (int it = 0; it < NS_TF; it++) {
        mm_tf(B0, B0, g, t, mb, nb, a4);  st_tf(B2, g, t, mb, nb, a4);
        __syncthreads();
        mm_tf(B2, B0, g, t, mb, nb, a4);  st_tf(B3, g, t, mb, nb, a4);
        __syncthreads();
        mm_tf(B3, B1, g, t, mb, nb, a4);
#pragma unroll
        for (int j = 0; j < 4; j++) {
            int c0 = nb + 8 * j + 2 * t;
            float2 p0 = *(const float2*)&B0[(mb + g)     * PN + c0];
            float2 p1 = *(const float2*)&B0[(mb + g + 8) * PN + c0];
            *(float2*)&B0[(mb + g)     * PN + c0] =
                make_float2(1.5f * p0.x - 0.5f * a4[j][0], 1.5f * p0.y - 0.5f * a4[j][1]);
            *(float2*)&B0[(mb + g + 8) * PN + c0] =
                make_float2(1.5f * p1.x - 0.5f * a4[j][2], 1.5f * p1.y - 0.5f * a4[j][3]);
        }
        __syncthreads();
    }

    // exact fp32 final iterations
    u64 acc[4][2];
    for (int it = 0; it < NS_FP; it++) {
        mm_sym(B0, B0, ib, jb, acc);  store4(B2, ib, jb, acc);
        __syncthreads();
        mm_sym(B2, B0, ib, jb, acc);  store4(B3, ib, jb, acc);
        __syncthreads();
        mm_sym(B3, B1, ib, jb, acc);
#pragma unroll
        for (int ii = 0; ii < 4; ii++) {
            float2 l0 = unpk(acc[ii][0]);
            float2 l1 = unpk(acc[ii][1]);
            int base = (ib + ii) * PN + jb;
            float4 p = *(const float4*)&B0[base];
            *(float4*)&B0[base] = make_float4(1.5f * p.x - 0.5f * l0.x,
                                              1.5f * p.y - 0.5f * l0.y,
                                              1.5f * p.z - 0.5f * l1.x,
                                              1.5f * p.w - 0.5f * l1.y);
        }
        __syncthreads();
    }

#pragma unroll
    for (int ii = 0; ii < 4; ii++) {
        float4 p = *(const float4*)&B0[(ib + ii) * PN + jb];
        *(float4*)&d_wm[(ib + ii) * 64 + jb] =
            make_float4(p.x * srt, p.y * srt, p.z * srt, p.w * srt);
    }
    if (tid < 64) {
        float s = 0.f;
#pragma unroll 8
        for (int j = 0; j < 64; j++) s += B0[tid * PN + j] * (d_sums[j] * inv_m);
        d_off[tid] = beta[tid] - srt * s;
    }
}

// ---------------------------------------------------------------------------
// Kernel 3: out = x + E@x + off  (E = wm - I, tf32 frags in registers).
// mma results staged through smem; final pass does vectorized coalesced
// float4 read-add-store (fixes R6's scattered-store wavefront blowup).
// ---------------------------------------------------------------------------
__global__ __launch_bounds__(256, 2) void apply_kernel(const float* __restrict__ X,
                                                       float* __restrict__ out) {
    __shared__ __align__(16) float xsh[2][64 * PA];
    __shared__ __align__(16) float ysh[64 * PA];
    __shared__ float osh[64];
    int tid = threadIdx.x, lane = tid & 31, w = tid >> 5;
    int g = lane >> 2, t = lane & 3;
    int mb = (w & 1) * 32, nb = (w >> 1) * 16;

    uint32_t sb[2];
    sb[0] = (uint32_t)__cvta_generic_to_shared(&xsh[0][0]);
    sb[1] = (uint32_t)__cvta_generic_to_shared(&xsh[1][0]);

    uint32_t ea[2][8][4];
#pragma unroll
    for (int mi = 0; mi < 2; mi++) {
        int r0 = mb + 16 * mi + g, r1 = r0 + 8;
#pragma unroll
        for (int ks = 0; ks < 8; ks++) {
            int c0 = 8 * ks + t, c1 = c0 + 4;
            ea[mi][ks][0] = tf32r(d_wm[r0 * 64 + c0] - (r0 == c0 ? 1.f : 0.f));
            ea[mi][ks][1] = tf32r(d_wm[r1 * 64 + c0] - (r1 == c0 ? 1.f : 0.f));
            ea[mi][ks][2] = tf32r(d_wm[r0 * 64 + c1] - (r0 == c1 ? 1.f : 0.f));
            ea[mi][ks][3] = tf32r(d_wm[r1 * 64 + c1] - (r1 == c1 ? 1.f : 0.f));
        }
    }
    if (tid < 64) osh[tid] = d_off[tid];

    {
        int ch = blockIdx.x;
        int b = ch / CPI, pc = (ch - b * CPI) * 64;
        const float* base = X + b * CCH * HWP + pc;
#pragma unroll
        for (int i = 0; i < 4; i++) {
            int f = tid + 256 * i;
            int c = f >> 4, q = f & 15;
            cpa16(sb[0] + (c * PA + q * 4) * 4, base + c * HWP + q * 4);
        }
        cp_commit();
    }

    int buf = 0;
    for (int ch = blockIdx.x; ch < NCHUNK; ch += GRIDB) {
        int cn = ch + GRIDB;
        if (cn < NCHUNK) {
            int b = cn / CPI, pc = (cn - b * CPI) * 64;
            const float* base = X + b * CCH * HWP + pc;
#pragma unroll
            for (int i = 0; i < 4; i++) {
                int f = tid + 256 * i;
                int c = f >> 4, q = f & 15;
                cpa16(sb[buf ^ 1] + (c * PA + q * 4) * 4, base + c * HWP + q * 4);
            }
            cp_commit();
            cp_wait1();
        } else {
            cp_wait0();
        }
        __syncthreads();

        const float* xb = &xsh[buf][0];
        float acc[2][2][4];
#pragma unroll
        for (int mi = 0; mi < 2; mi++)
#pragma unroll
            for (int j = 0; j < 2; j++)
#pragma unroll
                for (int e = 0; e < 4; e++) acc[mi][j][e] = 0.f;

#pragma unroll
        for (int ks = 0; ks < 8; ks++) {
            uint32_t b00 = fu(xb[(8 * ks + t)     * PA + nb + g]);
            uint32_t b01 = fu(xb[(8 * ks + t + 4) * PA + nb + g]);
            uint32_t b10 = fu(xb[(8 * ks + t)     * PA + nb + 8 + g]);
            uint32_t b11 = fu(xb[(8 * ks + t + 4) * PA + nb + 8 + g]);
#pragma unroll
            for (int mi = 0; mi < 2; mi++) {
                mma8(acc[mi][0], ea[mi][ks][0], ea[mi][ks][1],
                                 ea[mi][ks][2], ea[mi][ks][3], b00, b01);
                mma8(acc[mi][1], ea[mi][ks][0], ea[mi][ks][1],
                                 ea[mi][ks][2], ea[mi][ks][3], b10, b11);
            }
        }

        // stage E@x fragments into ysh
#pragma unroll
        for (int mi = 0; mi < 2; mi++) {
            int r0 = mb + 16 * mi + g, r1 = r0 + 8;
#pragma unroll
            for (int j = 0; j < 2; j++) {
                int cc = nb + 8 * j + 2 * t;
                *(float2*)&ysh[r0 * PA + cc] = make_float2(acc[mi][j][0], acc[mi][j][1]);
                *(float2*)&ysh[r1 * PA + cc] = make_float2(acc[mi][j][2], acc[mi][j][3]);
            }
        }
        __syncthreads();

        // coalesced output pass: out = x + E@x + off
        int b = ch / CPI, pc = (ch - b * CPI) * 64;
        float* ob = out + b * CCH * HWP + pc;
#pragma unroll
        for (int i = 0; i < 4; i++) {
            int f = tid + 256 * i;
            int c = f >> 4, q = f & 15;
            float4 xv = *(const float4*)&xb[c * PA + q * 4];
            float4 yv = *(const float4*)&ysh[c * PA + q * 4];
            float o = osh[c];
            *(float4*)(ob + c * HWP + q * 4) =
                make_float4(xv.x + yv.x + o, xv.y + yv.y + o,
                            xv.z + yv.z + o, xv.w + yv.w + o);
        }
        __syncthreads();
        buf ^= 1;
    }
}

extern "C" void kernel_launch(void* const* d_in, const int* in_sizes, int n_in,
                              void* d_out, int out_size) {
    (void)in_sizes; (void)n_in; (void)out_size;
    const float* X    = (const float*)d_in[0];
    const float* beta = (const float*)d_in[1];
    float* out        = (float*)d_out;

    gram_kernel<<<GRIDB, 256>>>(X);
    reduce_kernel<<<33, 128>>>();
    ns_kernel<<<1, 256>>>(beta);
    apply_kernel<<<GRIDB, 256>>>(X, out);
}